// round 1
// baseline (speedup 1.0000x reference)
#include <cuda_runtime.h>
#include <math.h>

// Fixed problem geometry (from setup_inputs: inp (8,3,224,224) fp32,
// tau_min=1, tau_max=60, ntau=8, num_angles=12, stride=2).
#define B_      8
#define F_      3
#define H_      224
#define W_      224
#define STRIDE_ 2
#define HS_     112   // (H-1)/stride + 1
#define WS_     112
#define NTAU_   8
#define NANG_   12
#define NOFF_   (NTAU_ * NANG_)

#define WS4_    (WS_ / 4)                               // 28 float4 per row
#define TOTAL4_ (B_ * F_ * NTAU_ * NANG_ * HS_ * WS4_)  // 7,225,344

__device__ float g_yoff[NOFF_];
__device__ float g_xoff[NOFF_];

// Compute log-polar offsets exactly as the reference does (float64 math,
// cast to float32). theta in [-pi, pi), tau log-spaced, angle-major ravel.
__global__ void compute_offsets_kernel() {
    int idx = threadIdx.x;
    if (idx < NOFF_) {
        int a = idx / NTAU_;   // angle-major
        int t = idx % NTAU_;
        double c     = pow(60.0, 1.0 / 7.0) - 1.0;      // (tau_max/tau_min)^(1/(ntau-1)) - 1
        double theta = (double)a * (2.0 * M_PI / (double)NANG_) - M_PI;
        double tau   = pow(1.0 + c, (double)t);         // tau_min = 1
        g_yoff[idx] = (float)(tau * sin(theta));
        g_xoff[idx] = (float)(tau * cos(theta));
    }
}

__global__ __launch_bounds__(256)
void logpolar_kernel(const float* __restrict__ inp, float4* __restrict__ out) {
    int idx4 = blockIdx.x * 256 + threadIdx.x;
    if (idx4 >= TOTAL4_) return;

    // Decompose linear float4 index: (((bf*T + t)*A + a)*Hs + i)*Ws4 + j4
    int j4 = idx4 % WS4_;
    int r  = idx4 / WS4_;
    int i  = r % HS_;   r /= HS_;
    int a  = r % NANG_; r /= NANG_;
    int t  = r % NTAU_;
    int bf = r / NTAU_;

    int   off = a * NTAU_ + t;           // offsets stored angle-major
    float yo  = g_yoff[off];
    float xo  = g_xoff[off];

    // Row (y) terms are shared across the 4 outputs.
    float yq  = (float)(i * STRIDE_) + yo;
    float y0f = floorf(yq);
    float wy  = yq - y0f;
    int   y0  = (int)y0f;
    bool  vr0 = (y0 >= 0)     && (y0 < H_);
    bool  vr1 = (y0 + 1 >= 0) && (y0 + 1 < H_);

    const float* base = inp + (size_t)bf * (H_ * W_);
    const float* row0 = base + y0 * W_;
    const float* row1 = row0 + W_;

    float4 res;
    float* rp = reinterpret_cast<float*>(&res);

    #pragma unroll
    for (int k = 0; k < 4; k++) {
        int   j   = j4 * 4 + k;
        float xq  = (float)(j * STRIDE_) + xo;
        float x0f = floorf(xq);
        float wx  = xq - x0f;
        int   x0  = (int)x0f;
        bool  vc0 = (x0 >= 0)     && (x0 < W_);
        bool  vc1 = (x0 + 1 >= 0) && (x0 + 1 < W_);

        float g00 = (vr0 && vc0) ? __ldg(row0 + x0)     : 0.0f;
        float g01 = (vr0 && vc1) ? __ldg(row0 + x0 + 1) : 0.0f;
        float g10 = (vr1 && vc0) ? __ldg(row1 + x0)     : 0.0f;
        float g11 = (vr1 && vc1) ? __ldg(row1 + x0 + 1) : 0.0f;

        float top = (1.0f - wx) * g00 + wx * g01;
        float bot = (1.0f - wx) * g10 + wx * g11;
        rp[k] = (1.0f - wy) * top + wy * bot;
    }

    out[idx4] = res;
}

extern "C" void kernel_launch(void* const* d_in, const int* in_sizes, int n_in,
                              void* d_out, int out_size) {
    const float* inp = (const float*)d_in[0];
    float4*      out = (float4*)d_out;

    compute_offsets_kernel<<<1, 128>>>();

    int blocks = (TOTAL4_ + 255) / 256;   // 28224
    logpolar_kernel<<<blocks, 256>>>(inp, out);
}

// round 2
// speedup vs baseline: 1.0536x; 1.0536x over previous
#include <cuda_runtime.h>
#include <math.h>

// Fixed problem geometry (setup_inputs: inp (8,3,224,224) fp32,
// tau_min=1, tau_max=60, ntau=8, num_angles=12, stride=2).
#define B_      8
#define F_      3
#define H_      224
#define W_      224
#define STRIDE_ 2
#define HS_     112
#define WS_     112
#define NTAU_   8
#define NANG_   12
#define NOFF_   (NTAU_ * NANG_)

#define TOTAL_  (B_ * F_ * NTAU_ * NANG_ * HS_ * WS_)   // 28,901,376 outputs

__device__ float g_yoff[NOFF_];
__device__ float g_xoff[NOFF_];

// Offsets exactly as the reference (float64 math, cast to float32).
__global__ void compute_offsets_kernel() {
    int idx = threadIdx.x;
    if (idx < NOFF_) {
        int a = idx / NTAU_;   // angle-major ravel
        int t = idx % NTAU_;
        double c     = pow(60.0, 1.0 / 7.0) - 1.0;
        double theta = (double)a * (2.0 * M_PI / (double)NANG_) - M_PI;
        double tau   = pow(1.0 + c, (double)t);
        g_yoff[idx] = (float)(tau * sin(theta));
        g_xoff[idx] = (float)(tau * cos(theta));
    }
}

// One thread = one output element; lane index maps to output column j so that
// a warp's gathers span only ~2 cache lines per load (x step = 8B per lane).
__global__ __launch_bounds__(256)
void logpolar_kernel(const float* __restrict__ inp, float* __restrict__ out) {
    int idx = blockIdx.x * 256 + threadIdx.x;
    if (idx >= TOTAL_) return;

    // idx = ((((bf*NTAU + t)*NANG + a)*HS + i)*WS + j)
    int j  = idx % WS_;
    int r  = idx / WS_;
    int i  = r % HS_;   r /= HS_;
    int a  = r % NANG_; r /= NANG_;
    int t  = r % NTAU_;
    int bf = r / NTAU_;

    int   off = a * NTAU_ + t;
    float yo  = g_yoff[off];   // uniform across warp -> broadcast
    float xo  = g_xoff[off];

    float yq  = (float)(i * STRIDE_) + yo;
    float y0f = floorf(yq);
    float wy  = yq - y0f;
    int   y0  = (int)y0f;
    bool  vr0 = (y0 >= 0)     && (y0 < H_);
    bool  vr1 = (y0 >= -1)    && (y0 < H_ - 1);

    float xq  = (float)(j * STRIDE_) + xo;
    float x0f = floorf(xq);
    float wx  = xq - x0f;
    int   x0  = (int)x0f;
    bool  vc0 = (x0 >= 0)     && (x0 < W_);
    bool  vc1 = (x0 >= -1)    && (x0 < W_ - 1);

    const float* row0 = inp + (size_t)bf * (H_ * W_) + y0 * W_;
    const float* row1 = row0 + W_;

    float g00 = (vr0 && vc0) ? __ldg(row0 + x0)     : 0.0f;
    float g01 = (vr0 && vc1) ? __ldg(row0 + x0 + 1) : 0.0f;
    float g10 = (vr1 && vc0) ? __ldg(row1 + x0)     : 0.0f;
    float g11 = (vr1 && vc1) ? __ldg(row1 + x0 + 1) : 0.0f;

    float top = g00 + wx * (g01 - g00);
    float bot = g10 + wx * (g11 - g10);
    out[idx]  = top + wy * (bot - top);
}

extern "C" void kernel_launch(void* const* d_in, const int* in_sizes, int n_in,
                              void* d_out, int out_size) {
    const float* inp = (const float*)d_in[0];
    float*       out = (float*)d_out;

    compute_offsets_kernel<<<1, 128>>>();

    int blocks = (TOTAL_ + 255) / 256;   // 112,896
    logpolar_kernel<<<blocks, 256>>>(inp, out);
}

// round 3
// speedup vs baseline: 2.2798x; 2.1638x over previous
#include <cuda_runtime.h>
#include <math.h>

// Fixed problem geometry (setup_inputs: inp (8,3,224,224) fp32,
// tau_min=1, tau_max=60, ntau=8, num_angles=12, stride=2).
#define B_      8
#define F_      3
#define H_      224
#define W_      224
#define HS_     112
#define WS_     112
#define NTAU_   8
#define NANG_   12
#define NOFF_   (NTAU_ * NANG_)
#define NGRP_   (B_ * F_ * NTAU_ * NANG_)   // 192 (bf,t,a) groups

#define I_PER_  16                           // i-rows per thread
#define NTILE_I (HS_ / I_PER_)               // 7

__device__ float g_yoff[NOFF_];
__device__ float g_xoff[NOFF_];

// Offsets exactly as the reference (float64 math, cast to float32).
__global__ void compute_offsets_kernel() {
    int idx = threadIdx.x;
    if (idx < NOFF_) {
        int a = idx / NTAU_;   // angle-major ravel
        int t = idx % NTAU_;
        double c     = pow(60.0, 1.0 / 7.0) - 1.0;
        double theta = (double)a * (2.0 * M_PI / (double)NANG_) - M_PI;
        double tau   = pow(1.0 + c, (double)t);
        g_yoff[idx] = (float)(tau * sin(theta));
        g_xoff[idx] = (float)(tau * cos(theta));
    }
}

// blockIdx.y = group g = ((bf*NTAU + t)*NANG + a); blockIdx.x = i-tile;
// threadIdx.x = output column j. Each thread emits I_PER_ outputs down i.
__global__ __launch_bounds__(128)
void logpolar_kernel(const float* __restrict__ inp, float* __restrict__ out) {
    int j = threadIdx.x;
    if (j >= WS_) return;

    int g  = blockIdx.y;                 // uniform per block
    int a  = g % NANG_;
    int t  = (g / NANG_) % NTAU_;
    int bf = g / (NANG_ * NTAU_);

    int   off = a * NTAU_ + t;
    float yo  = g_yoff[off];
    float xo  = g_xoff[off];

    // x-terms: computed once, reused for all 16 outputs.
    float xq  = (float)(2 * j) + xo;
    float x0f = floorf(xq);
    float wx  = xq - x0f;
    int   x0  = (int)x0f;
    bool  vc0 = (x0 >= 0)  && (x0 < W_);
    bool  vc1 = (x0 >= -1) && (x0 < W_ - 1);

    // y-terms: yq steps by exactly 2.0 per i, so floor once, then y0 += 2.
    int   i0  = blockIdx.x * I_PER_;
    float yq0 = (float)(2 * i0) + yo;
    float y0f = floorf(yq0);
    float wy  = yq0 - y0f;               // invariant along the i-loop
    int   y0  = (int)y0f;

    const float* base = inp + (size_t)bf * (H_ * W_);
    float* outp = out + (size_t)g * (HS_ * WS_) + (size_t)i0 * WS_ + j;

    #pragma unroll
    for (int m = 0; m < I_PER_; m++) {
        bool vr0 = (y0 >= 0)  && (y0 < H_);
        bool vr1 = (y0 >= -1) && (y0 < H_ - 1);

        const float* row0 = base + y0 * W_ + x0;
        const float* row1 = row0 + W_;

        float g00 = (vr0 && vc0) ? __ldg(row0)     : 0.0f;
        float g01 = (vr0 && vc1) ? __ldg(row0 + 1) : 0.0f;
        float g10 = (vr1 && vc0) ? __ldg(row1)     : 0.0f;
        float g11 = (vr1 && vc1) ? __ldg(row1 + 1) : 0.0f;

        float top = g00 + wx * (g01 - g00);
        float bot = g10 + wx * (g11 - g10);
        outp[0]   = top + wy * (bot - top);

        y0   += 2;
        outp += WS_;
    }
}

extern "C" void kernel_launch(void* const* d_in, const int* in_sizes, int n_in,
                              void* d_out, int out_size) {
    const float* inp = (const float*)d_in[0];
    float*       out = (float*)d_out;

    compute_offsets_kernel<<<1, 128>>>();

    dim3 grid(NTILE_I, NGRP_);   // (7, 192)
    logpolar_kernel<<<grid, 128>>>(inp, out);
}